// round 2
// baseline (speedup 1.0000x reference)
#include <cuda_runtime.h>
#include <math_constants.h>
#include <cstdint>

#define CCH 256
#define HW  65536     // 256*256 pixels
#define P_TILE 32

// ---------------- scratch (no allocations allowed) ----------------
__device__ float g_X[CCH * 256];       // X[c][n]  pooled support features
__device__ float g_protoT[CCH * 256];  // protoT[c][n]  normalized protos (transposed)
__device__ float g_mlo[CCH], g_mdi[CCH], g_mhi[CCH];
__device__ float g_sel[256];

// ---------------- reduction helpers ----------------
__device__ __forceinline__ float warp_sum(float v) {
#pragma unroll
    for (int o = 16; o; o >>= 1) v += __shfl_xor_sync(0xffffffffu, v, o);
    return v;
}
__device__ __forceinline__ float warp_max(float v) {
#pragma unroll
    for (int o = 16; o; o >>= 1) v = fmaxf(v, __shfl_xor_sync(0xffffffffu, v, o));
    return v;
}
__device__ __forceinline__ float blk_sum256(float v, float* s, int t) {
    v = warp_sum(v);
    __syncthreads();
    if ((t & 31) == 0) s[t >> 5] = v;
    __syncthreads();
    if (t < 32) {
        float x = (t < 8) ? s[t] : 0.f;
        x = warp_sum(x);
        if (t == 0) s[32] = x;
    }
    __syncthreads();
    float r = s[32];
    __syncthreads();
    return r;
}
__device__ __forceinline__ float blk_max256(float v, float* s, int t) {
    v = warp_max(v);
    __syncthreads();
    if ((t & 31) == 0) s[t >> 5] = v;
    __syncthreads();
    if (t < 32) {
        float x = (t < 8) ? s[t] : -CUDART_INF_F;
        x = warp_max(x);
        if (t == 0) s[32] = x;
    }
    __syncthreads();
    float r = s[32];
    __syncthreads();
    return r;
}

// ---------------- K1a: pool sup_x (16x16 avg) -> g_X[c][n] ----------------
// One block per channel c. Thread t owns image column w=t; accumulates the 16
// row-groups, then a shared transpose-reduce produces the 256 pooled outputs.
__global__ void pool_x_kernel(const float* __restrict__ sx) {
    int c = blockIdx.x, t = threadIdx.x;
    const float* base = sx + (size_t)c * HW + t;
    __shared__ float sm[16 * 256];
#pragma unroll
    for (int bh = 0; bh < 16; bh++) {
        float a = 0.f;
#pragma unroll
        for (int r = 0; r < 16; r++) a += base[(bh * 16 + r) * 256];
        sm[bh * 256 + t] = a;
    }
    __syncthreads();
    int bh = t >> 4, bw = t & 15;
    float s = 0.f;
#pragma unroll
    for (int k = 0; k < 16; k++) s += sm[bh * 256 + bw * 16 + k];
    g_X[c * 256 + t] = s * (1.f / 256.f);
}

// ---------------- K1b: pool sup_y -> sel[n] ----------------
__global__ void pool_y_kernel(const float* __restrict__ sy) {
    int t = threadIdx.x;
    const float* base = sy + t;
    __shared__ float sm[16 * 256];
#pragma unroll
    for (int bh = 0; bh < 16; bh++) {
        float a = 0.f;
#pragma unroll
        for (int r = 0; r < 16; r++) a += base[(bh * 16 + r) * 256];
        sm[bh * 256 + t] = a;
    }
    __syncthreads();
    int bh = t >> 4, bw = t & 15;
    float s = 0.f;
#pragma unroll
    for (int k = 0; k < 16; k++) s += sm[bh * 256 + bw * 16 + k];
    g_sel[t] = ((s * (1.f / 256.f)) > 0.5f) ? 1.f : 0.f;
}

// ---------------- K2: w1 row + softmax -> tridiagonal band of (A*cal) ----------------
// Block i computes row i of w1 = X X^T, its softmax max/sum, and writes the
// three band coefficients m_lo/m_di/m_hi (only band entries of soft are needed).
__global__ void band_kernel(const float* __restrict__ cal) {
    int i = blockIdx.x, t = threadIdx.x;
    __shared__ float xi[256];
    __shared__ float sred[40];
    xi[t] = g_X[i * 256 + t];
    __syncthreads();
    const float* xr = g_X + t * 256;
    float w = 0.f;
#pragma unroll 8
    for (int n = 0; n < 256; n++) w = fmaf(xi[n], xr[n], w);
    float mx = blk_max256(w, sred, t);
    float e = expf(w - mx);
    float S = blk_sum256(e, sred, t);
    if (t >= i - 1 && t <= i + 1) {
        float s = e / S;
        float m = cal[i * 256 + t] * (1.f + 0.2f * s);
        if (t == i - 1) g_mlo[i] = m;
        else if (t == i) g_mdi[i] = m;
        else g_mhi[i] = m;
    }
    if (t == 0) {
        if (i == 0)   g_mlo[0]   = 0.f;
        if (i == 255) g_mhi[255] = 0.f;
    }
}

// ---------------- K3: Xn = tridiag @ X, column-normalize -> protoT[c][n] ----------------
__global__ void proto_kernel() {
    int n = blockIdx.x, i = threadIdx.x;
    __shared__ float sred[40];
    float x0 = g_X[i * 256 + n];
    float xm = (i > 0)   ? g_X[(i - 1) * 256 + n] : 0.f;
    float xp = (i < 255) ? g_X[(i + 1) * 256 + n] : 0.f;
    float v = g_mlo[i] * xm + g_mdi[i] * x0 + g_mhi[i] * xp;
    float ss = blk_sum256(v * v, sred, i);
    float nrm = fmaxf(sqrtf(ss), 1e-4f);
    g_protoT[i * 256 + n] = v / nrm;
}

// ---------------- K4: fused dists + mask + softmax + pred + argmax ----------------
// Block owns 32 pixels; thread t owns proto n=t. Inner loop over c uses packed
// f32x2 FMAs (2x fp32 rate). buf is reused: q-tile during the GEMM, d-matrix after.
__global__ __launch_bounds__(256) void dist_kernel(const float* __restrict__ qry,
                                                   float* __restrict__ out) {
    int t = threadIdx.x;
    int p0 = blockIdx.x * P_TILE;
    __shared__ __align__(16) float buf[256 * P_TILE];
    __shared__ float partial[256];
    __shared__ float nrm[P_TILE];

    // load q tile (coalesced: warp covers one c-row of 32 pixels) + sumsq
    float ss = 0.f;
#pragma unroll
    for (int r = 0; r < 32; r++) {
        int idx = r * 256 + t;            // idx = c*32 + j
        float v = qry[(size_t)(idx >> 5) * HW + p0 + (idx & 31)];
        buf[idx] = v;
        ss += v * v;
    }
    partial[t] = ss;                      // thread t has fixed j = t&31
    __syncthreads();
    if (t < 32) {
        float s = 0.f;
#pragma unroll
        for (int k = 0; k < 8; k++) s += partial[t + 32 * k];
        nrm[t] = fmaxf(sqrtf(s), 1e-4f);
    }

    // main accumulation: acc[a] holds pixels (2a, 2a+1) packed as f32x2
    unsigned long long acc[16];
#pragma unroll
    for (int a = 0; a < 16; a++) acc[a] = 0ull;
    const float* pp = g_protoT + t;
#pragma unroll 4
    for (int c = 0; c < 256; c++) {
        float pt = __ldg(pp + (c << 8));
        unsigned int ptu = __float_as_uint(pt);
        unsigned long long pt2;
        asm("mov.b64 %0, {%1, %2};" : "=l"(pt2) : "r"(ptu), "r"(ptu));
        const ulonglong2* q2 = (const ulonglong2*)(buf + c * P_TILE);
#pragma unroll
        for (int u = 0; u < 8; u++) {
            ulonglong2 q = q2[u];
            asm("fma.rn.f32x2 %0, %1, %2, %0;" : "+l"(acc[2 * u])     : "l"(q.x), "l"(pt2));
            asm("fma.rn.f32x2 %0, %1, %2, %0;" : "+l"(acc[2 * u + 1]) : "l"(q.y), "l"(pt2));
        }
    }
    float selv = g_sel[t];
    __syncthreads();   // q reads done, nrm visible; buf now becomes d-matrix

    const float NEG = -1e9f;
#pragma unroll
    for (int a = 0; a < 16; a++) {
        unsigned int lo, hi;
        asm("mov.b64 {%0, %1}, %2;" : "=r"(lo), "=r"(hi) : "l"(acc[a]));
        int j0 = 2 * a, j1 = 2 * a + 1;
        float d0 = (selv > 0.f) ? __uint_as_float(lo) * (20.f / nrm[j0]) : NEG;
        float d1 = (selv > 0.f) ? __uint_as_float(hi) * (20.f / nrm[j1]) : NEG;
        buf[j0 * 256 + t] = d0;
        buf[j1 * 256 + t] = d1;
    }
    __syncthreads();

    // per-pixel softmax-weighted sum + first-tie argmax (jnp.argmax semantics)
    int w = t >> 5, lane = t & 31;
    for (int pix = w; pix < P_TILE; pix += 8) {
        const float* dp = buf + pix * 256;
        float bm = -CUDART_INF_F; int bi = 0;
#pragma unroll
        for (int k = 0; k < 8; k++) {
            int n = k * 32 + lane;
            float v = dp[n];
            if (v > bm) { bm = v; bi = n; }
        }
#pragma unroll
        for (int o = 16; o; o >>= 1) {
            float om = __shfl_xor_sync(0xffffffffu, bm, o);
            int   oi = __shfl_xor_sync(0xffffffffu, bi, o);
            if (om > bm || (om == bm && oi < bi)) { bm = om; bi = oi; }
        }
        float se = 0.f, sd = 0.f;
#pragma unroll
        for (int k = 0; k < 8; k++) {
            float v = dp[k * 32 + lane];
            float e = expf(v - bm);
            se += e; sd += e * v;
        }
        se = warp_sum(se); sd = warp_sum(sd);
        if (lane == 0) {
            out[p0 + pix]      = sd / se;       // pred_grid
            out[HW + p0 + pix] = (float)bi;     // debug_assign
        }
    }
}

// ---------------- launcher ----------------
extern "C" void kernel_launch(void* const* d_in, const int* in_sizes, int n_in,
                              void* d_out, int out_size) {
    const float* qry   = (const float*)d_in[0];   // (1,1,256,256,256)
    const float* sup_x = (const float*)d_in[1];   // (1,1,1,256,256,256)
    const float* sup_y = (const float*)d_in[2];   // (1,1,1,256,256)
    // d_in[3] = s_init_seed (unused by reference)
    const float* cal   = (const float*)d_in[4];   // (256,256)
    float* out = (float*)d_out;                   // 65536 pred + 65536 assign

    pool_x_kernel<<<256, 256>>>(sup_x);
    pool_y_kernel<<<1, 256>>>(sup_y);
    band_kernel<<<256, 256>>>(cal);
    proto_kernel<<<256, 256>>>();
    dist_kernel<<<HW / P_TILE, 256>>>(qry, out);
}